// round 1
// baseline (speedup 1.0000x reference)
#include <cuda_runtime.h>
#include <cuda_bf16.h>

// InvertiblePWL:
//   n = 100 points = linspace(-5, 5, 100)
//   delta_h[j-1]   = int_len * (exp(p[j]) + 0.001), j = 1..99
//   prefix[0]=0, prefix[j]=sum_{i<j} delta_h[i]
//   delta_bias[j]  = b + prefix[j]
//   index = #{ j : eps >= points[j] }  in 0..100
//   s = max(index-1, 0)
//   out = (eps - points[s]) * (exp(p[index])+0.001) + delta_bias[s]
//       = eps * A[index] + B[index]
// with A[i] = exp(p[i])+0.001, B[i] = delta_bias[s] - points[s]*A[i].

#define N_BINS 100

__device__ float2 g_AB[N_BINS + 1];

__global__ void setup_kernel(const float* __restrict__ p,
                             const float* __restrict__ b,
                             const float* __restrict__ points) {
    __shared__ float pref[N_BINS];       // prefix[0..99]
    const int t = threadIdx.x;           // 128 threads
    const float int_len = 10.0f / 99.0f;

    if (t == 0) pref[0] = 0.0f;
    if (t >= 1 && t < N_BINS) pref[t] = int_len * (expf(p[t]) + 0.001f);
    __syncthreads();

    // Hillis-Steele inclusive scan over pref[0..99]
    for (int off = 1; off < N_BINS; off <<= 1) {
        float v = 0.0f;
        if (t < N_BINS && t >= off) v = pref[t - off];
        __syncthreads();
        if (t < N_BINS) pref[t] += v;
        __syncthreads();
    }

    if (t <= N_BINS) {
        const float b0 = b[0];
        const int s = (t > 0) ? (t - 1) : 0;   // s in 0..99
        const float k = expf(p[t]) + 0.001f;
        float2 ab;
        ab.x = k;
        ab.y = (b0 + pref[s]) - points[s] * k;
        g_AB[t] = ab;
    }
}

__device__ __forceinline__ float pwl_one(float e, const float2* __restrict__ sAB,
                                         const float* __restrict__ sP) {
    const float inv_len = 99.0f / 10.0f;
    int idx = __float2int_rd((e + 5.0f) * inv_len) + 1;
    idx = max(0, min(idx, N_BINS));
    // Robust adjust against the actual points table (>=: matches (eps-points)>=0)
    while (idx < N_BINS && e >= sP[idx]) ++idx;
    while (idx > 0 && e < sP[idx - 1]) --idx;
    const float2 ab = sAB[idx];
    return fmaf(e, ab.x, ab.y);
}

__global__ void __launch_bounds__(256)
pwl_kernel(const float4* __restrict__ eps, const float* __restrict__ points,
           float4* __restrict__ out, int n4) {
    __shared__ float2 sAB[N_BINS + 1];
    __shared__ float sP[N_BINS];
    const int t = threadIdx.x;
    if (t <= N_BINS) sAB[t] = g_AB[t];
    if (t < N_BINS) sP[t] = points[t];
    __syncthreads();

    const int i = blockIdx.x * blockDim.x + t;
    if (i >= n4) return;

    const float4 e = eps[i];
    float4 r;
    r.x = pwl_one(e.x, sAB, sP);
    r.y = pwl_one(e.y, sAB, sP);
    r.z = pwl_one(e.z, sAB, sP);
    r.w = pwl_one(e.w, sAB, sP);
    out[i] = r;
}

extern "C" void kernel_launch(void* const* d_in, const int* in_sizes, int n_in,
                              void* d_out, int out_size) {
    const float* eps    = (const float*)d_in[0];   // [4000000]
    const float* p      = (const float*)d_in[1];   // [101]
    const float* b      = (const float*)d_in[2];   // [1]
    const float* points = (const float*)d_in[3];   // [100]
    float* out = (float*)d_out;

    setup_kernel<<<1, 128>>>(p, b, points);

    const int n4 = out_size / 4;                   // 1,000,000 (out_size divisible by 4)
    const int threads = 256;
    const int blocks = (n4 + threads - 1) / threads;
    pwl_kernel<<<blocks, threads>>>((const float4*)eps, points, (float4*)out, n4);
}

// round 2
// speedup vs baseline: 1.1599x; 1.1599x over previous
#include <cuda_runtime.h>
#include <cuda_bf16.h>

// InvertiblePWL, fully analytic index:
//   out = eps * A[index] + B[index]
//   A[i] = exp(p[i]) + 0.001
//   B[i] = (b + prefix[max(i-1,0)]) - points[max(i-1,0)] * A[i]
//   index = clamp(floor((eps+5) * 99/10) + 1, 0, 100)
// The PWL is continuous at breakpoints, so ULP-level disagreement with the
// reference's exact linspace comparison is harmless (< 1e-6 rel).

#define N_BINS 100

__device__ float2 g_AB[N_BINS + 1];

__global__ void setup_kernel(const float* __restrict__ p,
                             const float* __restrict__ b,
                             const float* __restrict__ points) {
    __shared__ float pref[N_BINS];       // prefix[0..99]
    const int t = threadIdx.x;           // 128 threads
    const float int_len = 10.0f / 99.0f;

    if (t == 0) pref[0] = 0.0f;
    if (t >= 1 && t < N_BINS) pref[t] = int_len * (expf(p[t]) + 0.001f);
    __syncthreads();

    // Hillis-Steele inclusive scan over pref[0..99]
    for (int off = 1; off < N_BINS; off <<= 1) {
        float v = 0.0f;
        if (t < N_BINS && t >= off) v = pref[t - off];
        __syncthreads();
        if (t < N_BINS) pref[t] += v;
        __syncthreads();
    }

    if (t <= N_BINS) {
        const float b0 = b[0];
        const int s = (t > 0) ? (t - 1) : 0;   // s in 0..99
        const float k = expf(p[t]) + 0.001f;
        float2 ab;
        ab.x = k;
        ab.y = (b0 + pref[s]) - points[s] * k;
        g_AB[t] = ab;
    }
}

__device__ __forceinline__ float pwl_one(float e, const float2* __restrict__ sAB) {
    // idx = floor((e+5)*9.9) + 1, clamped to [0, 100]
    int idx = __float2int_rd(fmaf(e, 9.9f, 49.5f)) + 1;
    idx = max(0, min(idx, N_BINS));
    const float2 ab = sAB[idx];
    return fmaf(e, ab.x, ab.y);
}

#define TPB 256
#define V   4   // float4s per thread

__global__ void __launch_bounds__(TPB)
pwl_kernel(const float4* __restrict__ eps, float4* __restrict__ out, int n4) {
    __shared__ float2 sAB[N_BINS + 1];
    const int t = threadIdx.x;
    if (t <= N_BINS) sAB[t] = g_AB[t];
    __syncthreads();

    const int base = blockIdx.x * (TPB * V) + t;

    // Front-batched independent loads (MLP=4)
    float4 e[V];
    bool ok[V];
#pragma unroll
    for (int j = 0; j < V; j++) {
        const int i = base + j * TPB;
        ok[j] = (i < n4);
        if (ok[j]) e[j] = eps[i];
    }

#pragma unroll
    for (int j = 0; j < V; j++) {
        if (!ok[j]) continue;
        float4 r;
        r.x = pwl_one(e[j].x, sAB);
        r.y = pwl_one(e[j].y, sAB);
        r.z = pwl_one(e[j].z, sAB);
        r.w = pwl_one(e[j].w, sAB);
        out[base + j * TPB] = r;
    }
}

extern "C" void kernel_launch(void* const* d_in, const int* in_sizes, int n_in,
                              void* d_out, int out_size) {
    const float* eps    = (const float*)d_in[0];   // [4000000]
    const float* p      = (const float*)d_in[1];   // [101]
    const float* b      = (const float*)d_in[2];   // [1]
    const float* points = (const float*)d_in[3];   // [100]
    float* out = (float*)d_out;

    setup_kernel<<<1, 128>>>(p, b, points);

    const int n4 = out_size / 4;                   // 1,000,000
    const int per_block = TPB * V;                 // 1024 float4s per block
    const int blocks = (n4 + per_block - 1) / per_block;
    pwl_kernel<<<blocks, TPB>>>((const float4*)eps, (float4*)out, n4);
}

// round 3
// speedup vs baseline: 1.1875x; 1.0238x over previous
#include <cuda_runtime.h>
#include <cuda_bf16.h>

// InvertiblePWL, single fused kernel:
//   out = eps * A[idx] + B[idx],  idx = clamp(floor((eps+5)*9.9)+1, 0, 100)
//   A[i] = exp(p[i]) + 0.001
//   B[i] = (b0 + pref[max(i-1,0)]) - points[max(i-1,0)] * A[i]
//   pref[j] = sum_{i=1..j} int_len*(exp(p[i])+0.001),  pref[0]=0
// Each WARP builds its own private table copy with a shuffle scan (no block
// sync), overlapped with the front-batched eps loads.

#define N_BINS 100
#define TPB    256
#define V      8            // float4s per thread
#define WPAD   104          // per-warp table stride (101 rounded up)

__device__ __forceinline__ float warp_incl_scan(float v, int lane) {
#pragma unroll
    for (int o = 1; o < 32; o <<= 1) {
        float u = __shfl_up_sync(0xFFFFFFFFu, v, o);
        if (lane >= o) v += u;
    }
    return v;
}

__global__ void __launch_bounds__(TPB, 4)
pwl_kernel(const float4* __restrict__ eps,
           const float*  __restrict__ p,
           const float*  __restrict__ b,
           const float*  __restrict__ points,
           float4* __restrict__ out, int n4) {
    __shared__ float2 sAB[(TPB / 32) * WPAD];

    const int t    = threadIdx.x;
    const int lane = t & 31;
    const int wid  = t >> 5;
    float2* wAB = sAB + wid * WPAD;

    const int base = blockIdx.x * (TPB * V) + t;

    // ---- Front-batched independent eps loads (MLP = 8), in flight while
    // ---- the table is computed below.
    float4 e[V];
#pragma unroll
    for (int j = 0; j < V; j++) {
        const int i = base + j * TPB;
        if (i < n4) e[j] = eps[i];
    }

    // ---- Per-warp table build: A[i], B[i] for i = 0..100.
    {
        const float int_len = 10.0f / 99.0f;
        const float b0 = b[0];
        float carry = 0.0f;
#pragma unroll
        for (int c = 0; c < 4; c++) {
            const int idx = c * 32 + lane;        // 0..127
            const bool val = (idx <= N_BINS);
            const float pv = val ? p[idx] : 0.0f;
            const float a  = expf(pv) + 0.001f;
            const float d  = (idx >= 1 && idx <= N_BINS - 1) ? int_len * a : 0.0f;
            const float incl = warp_incl_scan(d, lane) + carry;
            carry = __shfl_sync(0xFFFFFFFFu, incl, 31);
            if (val) {
                const int s = (idx > 0) ? (idx - 1) : 0;
                const float pts = points[s];
                wAB[idx] = make_float2(a, (b0 + (incl - d)) - pts * a);
            }
        }
    }
    __syncwarp();

    // ---- Gather + FMA + store.
    const float inv_len = 99.0f / 10.0f;
#pragma unroll
    for (int j = 0; j < V; j++) {
        const int i = base + j * TPB;
        if (i >= n4) continue;
        float4 r;
        {
            int ix = __float2int_rd(fmaf(e[j].x, inv_len, 49.5f)) + 1;
            ix = max(0, min(ix, N_BINS));
            const float2 ab = wAB[ix];
            r.x = fmaf(e[j].x, ab.x, ab.y);
        }
        {
            int ix = __float2int_rd(fmaf(e[j].y, inv_len, 49.5f)) + 1;
            ix = max(0, min(ix, N_BINS));
            const float2 ab = wAB[ix];
            r.y = fmaf(e[j].y, ab.x, ab.y);
        }
        {
            int ix = __float2int_rd(fmaf(e[j].z, inv_len, 49.5f)) + 1;
            ix = max(0, min(ix, N_BINS));
            const float2 ab = wAB[ix];
            r.z = fmaf(e[j].z, ab.x, ab.y);
        }
        {
            int ix = __float2int_rd(fmaf(e[j].w, inv_len, 49.5f)) + 1;
            ix = max(0, min(ix, N_BINS));
            const float2 ab = wAB[ix];
            r.w = fmaf(e[j].w, ab.x, ab.y);
        }
        out[i] = r;
    }
}

extern "C" void kernel_launch(void* const* d_in, const int* in_sizes, int n_in,
                              void* d_out, int out_size) {
    const float* eps    = (const float*)d_in[0];   // [4000000]
    const float* p      = (const float*)d_in[1];   // [101]
    const float* b      = (const float*)d_in[2];   // [1]
    const float* points = (const float*)d_in[3];   // [100]
    float* out = (float*)d_out;

    const int n4 = out_size / 4;                   // 1,000,000
    const int per_block = TPB * V;                 // 2048 float4s per block
    const int blocks = (n4 + per_block - 1) / per_block;  // 489 -> single wave
    pwl_kernel<<<blocks, TPB>>>((const float4*)eps, p, b, points,
                                (float4*)out, n4);
}

// round 4
// speedup vs baseline: 1.1910x; 1.0030x over previous
#include <cuda_runtime.h>
#include <cuda_bf16.h>

// InvertiblePWL, single fused kernel:
//   out = eps * A[idx] + B[idx],  idx = clamp(floor((eps+5)*9.9)+1, 0, 100)
//   A[i] = exp(p[i]) + 0.001
//   B[i] = (b0 + pref[max(i-1,0)]) - points[max(i-1,0)] * A[i]
//   pref[j] = sum_{i=1..j} int_len*(exp(p[i])+0.001),  pref[0]=0
// Warp 0 of each block builds the 101-entry table with a shuffle scan BEFORE
// issuing its own data loads (keeps register liveness disjoint). Worker warps
// front-batch 8 LDG.128 each and hide the build under their DRAM latency.

#define N_BINS 100
#define TPB    256
#define V      8            // float4s per thread

__global__ void __launch_bounds__(TPB)
pwl_kernel(const float4* __restrict__ eps,
           const float*  __restrict__ p,
           const float*  __restrict__ b,
           const float*  __restrict__ points,
           float4* __restrict__ out, int n4) {
    __shared__ float2 sAB[N_BINS + 1];

    const int t = threadIdx.x;

    // ---- Warp 0: build table (scan temporaries die before e[] is live).
    if (t < 32) {
        const float int_len = 10.0f / 99.0f;
        const float b0 = b[0];
        float carry = 0.0f;
#pragma unroll
        for (int c = 0; c < 4; c++) {
            const int idx = c * 32 + t;           // 0..127
            const bool val = (idx <= N_BINS);
            const float pv = val ? p[idx] : 0.0f;
            const float a  = expf(pv) + 0.001f;
            float d = (idx >= 1 && idx <= N_BINS - 1) ? int_len * a : 0.0f;
            // inclusive shuffle scan of d within the warp
            float incl = d;
#pragma unroll
            for (int o = 1; o < 32; o <<= 1) {
                float u = __shfl_up_sync(0xFFFFFFFFu, incl, o);
                if (t >= o) incl += u;
            }
            incl += carry;
            carry = __shfl_sync(0xFFFFFFFFu, incl, 31);
            if (val) {
                const int s = (idx > 0) ? (idx - 1) : 0;
                sAB[idx] = make_float2(a, (b0 + (incl - d)) - points[s] * a);
            }
        }
    }

    // ---- Front-batched independent eps loads (32 lines in flight per warp).
    const int base = blockIdx.x * (TPB * V) + t;
    float4 e[V];
#pragma unroll
    for (int j = 0; j < V; j++) {
        const int i = base + j * TPB;
        if (i < n4) e[j] = eps[i];
    }

    __syncthreads();   // table visible; loads stay in flight across BAR

    // ---- Gather + FMA + store.
    const float inv_len = 99.0f / 10.0f;
#pragma unroll
    for (int j = 0; j < V; j++) {
        const int i = base + j * TPB;
        if (i >= n4) continue;
        float4 r;
        {
            int ix = __float2int_rd(fmaf(e[j].x, inv_len, 49.5f)) + 1;
            ix = max(0, min(ix, N_BINS));
            const float2 ab = sAB[ix];
            r.x = fmaf(e[j].x, ab.x, ab.y);
        }
        {
            int ix = __float2int_rd(fmaf(e[j].y, inv_len, 49.5f)) + 1;
            ix = max(0, min(ix, N_BINS));
            const float2 ab = sAB[ix];
            r.y = fmaf(e[j].y, ab.x, ab.y);
        }
        {
            int ix = __float2int_rd(fmaf(e[j].z, inv_len, 49.5f)) + 1;
            ix = max(0, min(ix, N_BINS));
            const float2 ab = sAB[ix];
            r.z = fmaf(e[j].z, ab.x, ab.y);
        }
        {
            int ix = __float2int_rd(fmaf(e[j].w, inv_len, 49.5f)) + 1;
            ix = max(0, min(ix, N_BINS));
            const float2 ab = sAB[ix];
            r.w = fmaf(e[j].w, ab.x, ab.y);
        }
        out[i] = r;
    }
}

extern "C" void kernel_launch(void* const* d_in, const int* in_sizes, int n_in,
                              void* d_out, int out_size) {
    const float* eps    = (const float*)d_in[0];   // [4000000]
    const float* p      = (const float*)d_in[1];   // [101]
    const float* b      = (const float*)d_in[2];   // [1]
    const float* points = (const float*)d_in[3];   // [100]
    float* out = (float*)d_out;

    const int n4 = out_size / 4;                   // 1,000,000
    const int per_block = TPB * V;                 // 2048 float4s per block
    const int blocks = (n4 + per_block - 1) / per_block;  // 489
    pwl_kernel<<<blocks, TPB>>>((const float4*)eps, p, b, points,
                                (float4*)out, n4);
}

// round 5
// speedup vs baseline: 1.4669x; 1.2316x over previous
#include <cuda_runtime.h>
#include <cuda_bf16.h>

// InvertiblePWL, single fused kernel:
//   out = eps * A[idx] + B[idx],  idx = clamp(floor((eps+5)*9.9)+1, 0, 100)
//   A[i] = exp(p[i]) + 0.001
//   B[i] = (b0 + pref[max(i-1,0)]) - points[max(i-1,0)] * A[i]
// Warp 0 of each block builds the 101-entry table (shuffle scan); all warps
// front-batch their eps loads before the barrier so the build hides under
// load latency. V=2 keeps grid large (1954 CTAs) so occupancy ~100%.

#define N_BINS 100
#define TPB    256
#define V      2            // float4s per thread

__global__ void __launch_bounds__(TPB)
pwl_kernel(const float4* __restrict__ eps,
           const float*  __restrict__ p,
           const float*  __restrict__ b,
           const float*  __restrict__ points,
           float4* __restrict__ out, int n4) {
    __shared__ float2 sAB[N_BINS + 1];

    const int t = threadIdx.x;

    // ---- Warp 0: build table.
    if (t < 32) {
        const float int_len = 10.0f / 99.0f;
        const float b0 = b[0];
        float carry = 0.0f;
#pragma unroll
        for (int c = 0; c < 4; c++) {
            const int idx = c * 32 + t;           // 0..127
            const bool val = (idx <= N_BINS);
            const float pv = val ? p[idx] : 0.0f;
            const float a  = expf(pv) + 0.001f;
            float d = (idx >= 1 && idx <= N_BINS - 1) ? int_len * a : 0.0f;
            float incl = d;
#pragma unroll
            for (int o = 1; o < 32; o <<= 1) {
                float u = __shfl_up_sync(0xFFFFFFFFu, incl, o);
                if (t >= o) incl += u;
            }
            incl += carry;
            carry = __shfl_sync(0xFFFFFFFFu, incl, 31);
            if (val) {
                const int s = (idx > 0) ? (idx - 1) : 0;
                sAB[idx] = make_float2(a, (b0 + (incl - d)) - points[s] * a);
            }
        }
    }

    // ---- Front-batched eps loads (in flight across the barrier).
    const int base = blockIdx.x * (TPB * V) + t;
    float4 e[V];
#pragma unroll
    for (int j = 0; j < V; j++) {
        const int i = base + j * TPB;
        if (i < n4) e[j] = eps[i];
    }

    __syncthreads();

    // ---- Gather + FMA + store.
    const float inv_len = 99.0f / 10.0f;
#pragma unroll
    for (int j = 0; j < V; j++) {
        const int i = base + j * TPB;
        if (i >= n4) continue;
        float4 r;
        {
            int ix = __float2int_rd(fmaf(e[j].x, inv_len, 49.5f)) + 1;
            ix = max(0, min(ix, N_BINS));
            const float2 ab = sAB[ix];
            r.x = fmaf(e[j].x, ab.x, ab.y);
        }
        {
            int ix = __float2int_rd(fmaf(e[j].y, inv_len, 49.5f)) + 1;
            ix = max(0, min(ix, N_BINS));
            const float2 ab = sAB[ix];
            r.y = fmaf(e[j].y, ab.x, ab.y);
        }
        {
            int ix = __float2int_rd(fmaf(e[j].z, inv_len, 49.5f)) + 1;
            ix = max(0, min(ix, N_BINS));
            const float2 ab = sAB[ix];
            r.z = fmaf(e[j].z, ab.x, ab.y);
        }
        {
            int ix = __float2int_rd(fmaf(e[j].w, inv_len, 49.5f)) + 1;
            ix = max(0, min(ix, N_BINS));
            const float2 ab = sAB[ix];
            r.w = fmaf(e[j].w, ab.x, ab.y);
        }
        out[i] = r;
    }
}

extern "C" void kernel_launch(void* const* d_in, const int* in_sizes, int n_in,
                              void* d_out, int out_size) {
    const float* eps    = (const float*)d_in[0];   // [4000000]
    const float* p      = (const float*)d_in[1];   // [101]
    const float* b      = (const float*)d_in[2];   // [1]
    const float* points = (const float*)d_in[3];   // [100]
    float* out = (float*)d_out;

    const int n4 = out_size / 4;                   // 1,000,000
    const int per_block = TPB * V;                 // 512 float4s per block
    const int blocks = (n4 + per_block - 1) / per_block;  // 1954
    pwl_kernel<<<blocks, TPB>>>((const float4*)eps, p, b, points,
                                (float4*)out, n4);
}